// round 1
// baseline (speedup 1.0000x reference)
#include <cuda_runtime.h>
#include <math.h>

#define TOK    4096
#define HID    3584
#define NQH    28
#define NKVH   4
#define HDIM   128
#define SEQL   1024
#define GQA    7
#define QSCALE 0.08838834764831845f   // 1/sqrt(128)

// ---------------- scratch (device globals; no allocation allowed) ----------------
__device__ float g_qraw[(size_t)TOK * NQH * HDIM];   // roped+scaled Q
__device__ float g_kraw[(size_t)TOK * NKVH * HDIM];  // raw K (pre-rope)
__device__ float g_vraw[(size_t)TOK * NKVH * HDIM];  // raw V
__device__ float g_attn[(size_t)TOK * NQH * HDIM];   // attention output

// ---------------- 128x128x16 fp32 SGEMM, 256 threads, 8x8 per thread ----------------
template <bool HAS_BIAS>
__global__ __launch_bounds__(256, 2) void sgemm128(
    const float* __restrict__ A, const float* __restrict__ B,
    const float* __restrict__ bias, float* __restrict__ C,
    int M, int N, int K)
{
    __shared__ float As[16][128];   // transposed A tile: As[k][m]
    __shared__ float Bs[16][128];   // Bs[k][n]

    const int tid = threadIdx.x;
    const int tx  = tid & 15;
    const int ty  = tid >> 4;
    const int bn  = blockIdx.x * 128;
    const int bm  = blockIdx.y * 128;

    float acc[2][2][4][4];
#pragma unroll
    for (int ri = 0; ri < 2; ri++)
#pragma unroll
        for (int rj = 0; rj < 2; rj++)
#pragma unroll
            for (int i = 0; i < 4; i++)
#pragma unroll
                for (int j = 0; j < 4; j++) acc[ri][rj][i][j] = 0.f;

    const float* Ap = A + (size_t)bm * K;
    const float* Bp = B + bn;

    for (int k0 = 0; k0 < K; k0 += 16) {
        // load A tile (128 rows x 16 k), store transposed
#pragma unroll
        for (int u = 0; u < 2; u++) {
            int s = tid + u * 256;            // 512 float4 slots
            int r = s >> 2;                   // 0..127
            int c = (s & 3) * 4;              // 0,4,8,12
            float4 v = *(const float4*)(Ap + (size_t)r * K + k0 + c);
            As[c + 0][r] = v.x; As[c + 1][r] = v.y;
            As[c + 2][r] = v.z; As[c + 3][r] = v.w;
        }
        // load B tile (16 k x 128 cols)
#pragma unroll
        for (int u = 0; u < 2; u++) {
            int s = tid + u * 256;
            int r = s >> 5;                   // 0..15
            int c = (s & 31) * 4;             // 0..124
            *(float4*)&Bs[r][c] = *(const float4*)(Bp + (size_t)(k0 + r) * N + c);
        }
        __syncthreads();
#pragma unroll
        for (int k = 0; k < 16; k++) {
            float4 a0 = *(const float4*)&As[k][ty * 4];
            float4 a1 = *(const float4*)&As[k][64 + ty * 4];
            float4 b0 = *(const float4*)&Bs[k][tx * 4];
            float4 b1 = *(const float4*)&Bs[k][64 + tx * 4];
            float ra[2][4] = {{a0.x, a0.y, a0.z, a0.w}, {a1.x, a1.y, a1.z, a1.w}};
            float rb[2][4] = {{b0.x, b0.y, b0.z, b0.w}, {b1.x, b1.y, b1.z, b1.w}};
#pragma unroll
            for (int ri = 0; ri < 2; ri++)
#pragma unroll
                for (int rj = 0; rj < 2; rj++)
#pragma unroll
                    for (int i = 0; i < 4; i++)
#pragma unroll
                        for (int j = 0; j < 4; j++)
                            acc[ri][rj][i][j] += ra[ri][i] * rb[rj][j];
        }
        __syncthreads();
    }

#pragma unroll
    for (int ri = 0; ri < 2; ri++)
#pragma unroll
        for (int i = 0; i < 4; i++) {
            int row = bm + ri * 64 + ty * 4 + i;
#pragma unroll
            for (int rj = 0; rj < 2; rj++) {
                int col = bn + rj * 64 + tx * 4;
                float4 o;
                o.x = acc[ri][rj][i][0]; o.y = acc[ri][rj][i][1];
                o.z = acc[ri][rj][i][2]; o.w = acc[ri][rj][i][3];
                if (HAS_BIAS) {
                    o.x += bias[col + 0]; o.y += bias[col + 1];
                    o.z += bias[col + 2]; o.w += bias[col + 3];
                }
                *(float4*)(C + (size_t)row * N + col) = o;
            }
        }
}

// ---------------- RoPE (neox) + kv_fused scatter ----------------
// idx space: t in [0,4096), h in [0,36), d in [0,64)
//   h <  28 : rope q head h in place (and fold in attention scale)
//   28<=h<32: rope k head h-28 -> kv_out[t][h-28][:]
//   32<=h<36: copy v head h-32 -> kv_out[t][4 + h-32][:]
__global__ void rope_scatter(const int* __restrict__ positions,
                             float* __restrict__ kv_out)
{
    int idx = blockIdx.x * blockDim.x + threadIdx.x;
    const int total = TOK * 36 * 64;
    if (idx >= total) return;
    int d = idx & 63;
    int h = (idx >> 6) % 36;
    int t = idx / (36 * 64);

    if (h >= 32) {
        int vh = h - 32;
        const float* src = g_vraw + (size_t)t * (NKVH * HDIM) + vh * HDIM;
        float* dst = kv_out + ((size_t)t * 8 + 4 + vh) * HDIM;
        dst[d]      = src[d];
        dst[d + 64] = src[d + 64];
        return;
    }

    int pos = positions[t];
    // inv_freq = theta^(-d/64); double precision to keep angle error ~fp32 ulp
    double inv = exp(-(double)d * (13.815510557964274 / 64.0));  // ln(1e6)=13.8155...
    float ang = (float)((double)pos * inv);
    float sv, cv;
    sincosf(ang, &sv, &cv);

    if (h < 28) {
        float* base = g_qraw + (size_t)t * (NQH * HDIM) + h * HDIM;
        float x1 = base[d], x2 = base[d + 64];
        base[d]      = (x1 * cv - x2 * sv) * QSCALE;
        base[d + 64] = (x2 * cv + x1 * sv) * QSCALE;
    } else {
        int kh = h - 28;
        const float* src = g_kraw + (size_t)t * (NKVH * HDIM) + kh * HDIM;
        float x1 = src[d], x2 = src[d + 64];
        float* dst = kv_out + ((size_t)t * 8 + kh) * HDIM;
        dst[d]      = x1 * cv - x2 * sv;
        dst[d + 64] = x2 * cv + x1 * sv;
    }
}

// ---------------- causal GQA flash attention (fp32) ----------------
// grid: (16 q-tiles, 28 q-heads, 4 batches), 256 threads
// tiles: 64 q rows x 64 k rows, online softmax.
// score ownership strided: thread (tx,ty) owns rows {ty+16i}, cols {tx+16j} (i,j<4)
// PV   ownership: rows {ty+16i}, cols tx*8..tx*8+7
#define ATTN_SMEM_FLOATS (2 * 64 * 132 + 64 * 128 + 64 * 65)
#define ATTN_SMEM_BYTES  (ATTN_SMEM_FLOATS * 4)

__global__ __launch_bounds__(256) void attn_kernel(const float* __restrict__ kv)
{
    extern __shared__ float sm[];
    float (*Qs)[132] = (float (*)[132])(sm);
    float (*Ks)[132] = (float (*)[132])(sm + 64 * 132);
    float (*Vs)[128] = (float (*)[128])(sm + 2 * 64 * 132);
    float (*Ps)[65]  = (float (*)[65]) (sm + 2 * 64 * 132 + 64 * 128);

    const int qt  = blockIdx.x;
    const int qh  = blockIdx.y;
    const int b   = blockIdx.z;
    const int kvh = qh / GQA;
    const int tid = threadIdx.x;
    const int tx  = tid & 15;
    const int ty  = tid >> 4;
    const int t0  = b * SEQL + qt * 64;

    // load Q tile (already roped + scaled)
    for (int s = tid; s < 64 * 32; s += 256) {
        int r = s >> 5, c = (s & 31) * 4;
        float4 v = *(const float4*)(g_qraw + ((size_t)(t0 + r) * NQH + qh) * HDIM + c);
        *(float4*)&Qs[r][c] = v;   // stride 132 floats keeps float4 aligned
    }

    float m_run[4], l_run[4], acc[4][8];
#pragma unroll
    for (int i = 0; i < 4; i++) {
        m_run[i] = -1e30f; l_run[i] = 0.f;
#pragma unroll
        for (int j = 0; j < 8; j++) acc[i][j] = 0.f;
    }

    for (int kt = 0; kt <= qt; kt++) {
        __syncthreads();   // Q-load visible (first iter) / previous PV done
        // load K and V tiles
        for (int s = tid; s < 64 * 32; s += 256) {
            int r = s >> 5, c = (s & 31) * 4;
            int t = b * SEQL + kt * 64 + r;
            *(float4*)&Ks[r][c] = *(const float4*)(kv + ((size_t)t * 8 + kvh) * HDIM + c);
            *(float4*)&Vs[r][c] = *(const float4*)(kv + ((size_t)t * 8 + 4 + kvh) * HDIM + c);
        }
        __syncthreads();

        // scores S = Q K^T   (4x4 per thread, strided)
        float sc[4][4];
#pragma unroll
        for (int i = 0; i < 4; i++)
#pragma unroll
            for (int j = 0; j < 4; j++) sc[i][j] = 0.f;

        for (int c = 0; c < HDIM; c += 4) {
            float4 qv[4], kk[4];
#pragma unroll
            for (int i = 0; i < 4; i++) qv[i] = *(const float4*)&Qs[ty + 16 * i][c];
#pragma unroll
            for (int j = 0; j < 4; j++) kk[j] = *(const float4*)&Ks[tx + 16 * j][c];
#pragma unroll
            for (int i = 0; i < 4; i++)
#pragma unroll
                for (int j = 0; j < 4; j++)
                    sc[i][j] += qv[i].x * kk[j].x + qv[i].y * kk[j].y +
                                qv[i].z * kk[j].z + qv[i].w * kk[j].w;
        }

        if (kt == qt) {   // causal mask on the diagonal tile
#pragma unroll
            for (int i = 0; i < 4; i++)
#pragma unroll
                for (int j = 0; j < 4; j++)
                    if (tx + 16 * j > ty + 16 * i) sc[i][j] = -1e30f;
        }

        // online softmax update per owned row
#pragma unroll
        for (int i = 0; i < 4; i++) {
            float mloc = fmaxf(fmaxf(sc[i][0], sc[i][1]), fmaxf(sc[i][2], sc[i][3]));
#pragma unroll
            for (int off = 8; off >= 1; off >>= 1)
                mloc = fmaxf(mloc, __shfl_xor_sync(0xffffffffu, mloc, off));
            float m_new = fmaxf(m_run[i], mloc);
            float alpha = __expf(m_run[i] - m_new);
            m_run[i] = m_new;
            float psum = 0.f;
#pragma unroll
            for (int j = 0; j < 4; j++) {
                float p = __expf(sc[i][j] - m_new);
                Ps[ty + 16 * i][tx + 16 * j] = p;
                psum += p;
            }
#pragma unroll
            for (int off = 8; off >= 1; off >>= 1)
                psum += __shfl_xor_sync(0xffffffffu, psum, off);
            l_run[i] = l_run[i] * alpha + psum;
#pragma unroll
            for (int j = 0; j < 8; j++) acc[i][j] *= alpha;
        }
        __syncthreads();   // Ps visible to all

        // acc += P V
        for (int k = 0; k < 64; k++) {
            float4 v0 = *(const float4*)&Vs[k][tx * 8];
            float4 v1 = *(const float4*)&Vs[k][tx * 8 + 4];
#pragma unroll
            for (int i = 0; i < 4; i++) {
                float p = Ps[ty + 16 * i][k];
                acc[i][0] += p * v0.x; acc[i][1] += p * v0.y;
                acc[i][2] += p * v0.z; acc[i][3] += p * v0.w;
                acc[i][4] += p * v1.x; acc[i][5] += p * v1.y;
                acc[i][6] += p * v1.z; acc[i][7] += p * v1.w;
            }
        }
    }

    // normalize + write [T, NQ*HD]
#pragma unroll
    for (int i = 0; i < 4; i++) {
        float inv_l = 1.f / l_run[i];
        int row = t0 + ty + 16 * i;
        float* dst = g_attn + (size_t)row * HID + qh * HDIM + tx * 8;
        float4 o0, o1;
        o0.x = acc[i][0] * inv_l; o0.y = acc[i][1] * inv_l;
        o0.z = acc[i][2] * inv_l; o0.w = acc[i][3] * inv_l;
        o1.x = acc[i][4] * inv_l; o1.y = acc[i][5] * inv_l;
        o1.z = acc[i][6] * inv_l; o1.w = acc[i][7] * inv_l;
        *(float4*)(dst)     = o0;
        *(float4*)(dst + 4) = o1;
    }
}

// ---------------- launch ----------------
extern "C" void kernel_launch(void* const* d_in, const int* in_sizes, int n_in,
                              void* d_out, int out_size)
{
    const float* hidden    = (const float*)d_in[0];
    const int*   positions = (const int*)  d_in[1];
    const float* wq        = (const float*)d_in[2];
    const float* bq        = (const float*)d_in[3];
    const float* wk        = (const float*)d_in[4];
    const float* bk        = (const float*)d_in[5];
    const float* wv        = (const float*)d_in[6];
    const float* bv        = (const float*)d_in[7];
    const float* wo        = (const float*)d_in[8];
    (void)in_sizes; (void)n_in; (void)out_size;

    float* out    = (float*)d_out;                       // [T, HID]
    float* out_kv = out + (size_t)TOK * HID;             // [T, 8, 128] kv_fused

    float *qraw, *kraw, *vraw, *attnb;
    cudaGetSymbolAddress((void**)&qraw,  g_qraw);
    cudaGetSymbolAddress((void**)&kraw,  g_kraw);
    cudaGetSymbolAddress((void**)&vraw,  g_vraw);
    cudaGetSymbolAddress((void**)&attnb, g_attn);

    cudaFuncSetAttribute(attn_kernel,
                         cudaFuncAttributeMaxDynamicSharedMemorySize,
                         ATTN_SMEM_BYTES);

    // QKV projections (+bias)
    sgemm128<true><<<dim3(HID / 128, TOK / 128), 256>>>(hidden, wq, bq, qraw, TOK, HID, HID);
    sgemm128<true><<<dim3((NKVH * HDIM) / 128, TOK / 128), 256>>>(hidden, wk, bk, kraw, TOK, NKVH * HDIM, HID);
    sgemm128<true><<<dim3((NKVH * HDIM) / 128, TOK / 128), 256>>>(hidden, wv, bv, vraw, TOK, NKVH * HDIM, HID);

    // RoPE q/k (+scale on q), write kv_fused output
    rope_scatter<<<(TOK * 36 * 64 + 255) / 256, 256>>>(positions, out_kv);

    // causal GQA flash attention
    attn_kernel<<<dim3(SEQL / 64, NQH, 4), 256, ATTN_SMEM_BYTES>>>(out_kv);

    // o_proj (no bias) -> first output
    sgemm128<false><<<dim3(HID / 128, TOK / 128), 256>>>(attnb, wo, nullptr, out, TOK, HID, HID);
}

// round 3
// speedup vs baseline: 1.7969x; 1.7969x over previous
#include <cuda_runtime.h>
#include <cuda_bf16.h>
#include <math.h>
#include <stdint.h>

#define TOK    4096
#define HID    3584
#define NQH    28
#define NKVH   4
#define HDIM   128
#define SEQL   1024
#define GQA    7
#define QSCALE 0.08838834764831845f   // 1/sqrt(128)
#define NQK    (NQH * HDIM)           // 3584
#define NKVD   (NKVH * HDIM)          // 512

// ---------------- scratch (device globals; no allocation allowed) ----------------
__device__ float g_qraw[(size_t)TOK * NQK];     // roped+scaled Q
__device__ float g_kraw[(size_t)TOK * NKVD];    // raw K (pre-rope)
__device__ float g_vraw[(size_t)TOK * NKVD];    // raw V
__device__ float g_attn[(size_t)TOK * NQK];     // attention output (fp32)

// bf16 split operands
__device__ __nv_bfloat16 g_hid_hi[(size_t)TOK * HID];
__device__ __nv_bfloat16 g_hid_lo[(size_t)TOK * HID];
__device__ __nv_bfloat16 g_wqt_hi[(size_t)NQK * HID];
__device__ __nv_bfloat16 g_wqt_lo[(size_t)NQK * HID];
__device__ __nv_bfloat16 g_wkt_hi[(size_t)NKVD * HID];
__device__ __nv_bfloat16 g_wkt_lo[(size_t)NKVD * HID];
__device__ __nv_bfloat16 g_wvt_hi[(size_t)NKVD * HID];
__device__ __nv_bfloat16 g_wvt_lo[(size_t)NKVD * HID];
__device__ __nv_bfloat16 g_wot_hi[(size_t)HID * NQK];
__device__ __nv_bfloat16 g_wot_lo[(size_t)HID * NQK];
__device__ __nv_bfloat16 g_att_hi[(size_t)TOK * NQK];
__device__ __nv_bfloat16 g_att_lo[(size_t)TOK * NQK];

// ==================== PTX helpers (arch-portable: mma.sync / ldmatrix / cp.async) ==========
__device__ __forceinline__ uint32_t smem_to_u32(const void* p) {
    uint32_t a;
    asm("{ .reg .u64 t; cvta.to.shared.u64 t, %1; cvt.u32.u64 %0, t; }" : "=r"(a) : "l"(p));
    return a;
}
#define CP_ASYNC16(dst, src) \
    asm volatile("cp.async.cg.shared.global [%0], [%1], 16;" :: "r"(dst), "l"(src))
#define CP_COMMIT() asm volatile("cp.async.commit_group;" ::: "memory")
#define CP_WAIT2()  asm volatile("cp.async.wait_group 2;" ::: "memory")

#define LDSM4(r, addr) \
    asm volatile("ldmatrix.sync.aligned.m8n8.x4.shared.b16 {%0,%1,%2,%3}, [%4];" \
        : "=r"((r)[0]), "=r"((r)[1]), "=r"((r)[2]), "=r"((r)[3]) : "r"(addr))

#define MMA16816(d, a, b0, b1) \
    asm volatile("mma.sync.aligned.m16n8k16.row.col.f32.bf16.bf16.f32 " \
        "{%0,%1,%2,%3}, {%4,%5,%6,%7}, {%8,%9}, {%0,%1,%2,%3};" \
        : "+f"((d)[0]), "+f"((d)[1]), "+f"((d)[2]), "+f"((d)[3]) \
        : "r"((a)[0]), "r"((a)[1]), "r"((a)[2]), "r"((a)[3]), "r"(b0), "r"(b1))

// ==================== split/convert kernels ====================
__global__ void split_convert(const float* __restrict__ src,
                              __nv_bfloat16* __restrict__ hi,
                              __nv_bfloat16* __restrict__ lo, int n)
{
    int i = (blockIdx.x * blockDim.x + threadIdx.x) * 4;
    if (i >= n) return;
    float4 v = *(const float4*)(src + i);
    __nv_bfloat16 h0 = __float2bfloat16(v.x), h1 = __float2bfloat16(v.y);
    __nv_bfloat16 h2 = __float2bfloat16(v.z), h3 = __float2bfloat16(v.w);
    __nv_bfloat16 l0 = __float2bfloat16(v.x - __bfloat162float(h0));
    __nv_bfloat16 l1 = __float2bfloat16(v.y - __bfloat162float(h1));
    __nv_bfloat16 l2 = __float2bfloat16(v.z - __bfloat162float(h2));
    __nv_bfloat16 l3 = __float2bfloat16(v.w - __bfloat162float(h3));
    *(__nv_bfloat162*)(hi + i)     = __nv_bfloat162(h0, h1);
    *(__nv_bfloat162*)(hi + i + 2) = __nv_bfloat162(h2, h3);
    *(__nv_bfloat162*)(lo + i)     = __nv_bfloat162(l0, l1);
    *(__nv_bfloat162*)(lo + i + 2) = __nv_bfloat162(l2, l3);
}

// src [R, C] fp32 -> dst [C, R] bf16 hi/lo  (dst[c][r] = src[r][c])
__global__ void split_transpose(const float* __restrict__ src,
                                __nv_bfloat16* __restrict__ hi,
                                __nv_bfloat16* __restrict__ lo, int R, int C)
{
    __shared__ float t[32][33];
    const int tx = threadIdx.x & 31;
    const int ty = threadIdx.x >> 5;      // 0..7
    const int r0 = blockIdx.y * 32;
    const int c0 = blockIdx.x * 32;
#pragma unroll
    for (int i = 0; i < 4; i++) {
        int r = ty + 8 * i;
        t[r][tx] = src[(size_t)(r0 + r) * C + c0 + tx];
    }
    __syncthreads();
#pragma unroll
    for (int i = 0; i < 4; i++) {
        int r = ty + 8 * i;               // output row = c0 + r
        float x = t[tx][r];
        __nv_bfloat16 h = __float2bfloat16(x);
        __nv_bfloat16 l = __float2bfloat16(x - __bfloat162float(h));
        size_t o = (size_t)(c0 + r) * R + r0 + tx;
        hi[o] = h;
        lo[o] = l;
    }
}

// ==================== HMMA bf16x3 GEMM, 128x128 tile ====================
// C[M,N] = A[M,K] * B[N,K]^T (+bias). 8 warps (2 M x 4 N), warp tile 64x32.
// smem/stage: Ahi,Alo,Bhi,Blo each 128x32 bf16 = 8KB -> 32KB; 4 stages = 128KB.
// swizzle: 64B rows, 4x16B chunks, chunk ^= (r ^ (r>>2)) & 3.
#define GSTAGE_B 32768
#define GSMEM_B  (4 * GSTAGE_B)

template <bool HAS_BIAS>
__global__ __launch_bounds__(256, 1) void gemm_hmma(
    const __nv_bfloat16* __restrict__ Ahi, const __nv_bfloat16* __restrict__ Alo,
    const __nv_bfloat16* __restrict__ Bhi, const __nv_bfloat16* __restrict__ Blo,
    const float* __restrict__ bias, float* __restrict__ C, int N, int K)
{
    extern __shared__ char smem[];
    const uint32_t sb = smem_to_u32(smem);
    const int tid  = threadIdx.x;
    const int wid  = tid >> 5;
    const int lane = tid & 31;
    const int bn   = blockIdx.x * 128;
    const int bm   = blockIdx.y * 128;
    const int m0   = (wid >> 2) * 64;   // warp M origin within tile
    const int n0   = (wid & 3) * 32;    // warp N origin within tile

    // per-thread ldmatrix offsets (within one operand buffer)
    uint32_t offA[4][2], offB[2][2];
#pragma unroll
    for (int i = 0; i < 4; i++)
#pragma unroll
        for (int ks = 0; ks < 2; ks++) {
            int row = m0 + i * 16 + (lane & 15);
            int ch  = (ks * 2 + (lane >> 4)) ^ ((row ^ (row >> 2)) & 3);
            offA[i][ks] = row * 64 + ch * 16;
        }
#pragma unroll
    for (int p = 0; p < 2; p++)
#pragma unroll
        for (int ks = 0; ks < 2; ks++) {
            int row = n0 + p * 16 + ((lane >> 3) & 1) * 8 + (lane & 7);
            int ch  = (ks * 2 + (lane >> 4)) ^ ((row ^ (row >> 2)) & 3);
            offB[p][ks] = row * 64 + ch * 16;
        }

    float acc[4][4][4];
#pragma unroll
    for (int i = 0; i < 4; i++)
#pragma unroll
        for (int j = 0; j < 4; j++)
#pragma unroll
            for (int r = 0; r < 4; r++) acc[i][j][r] = 0.f;

    // stage loader: 2048 x 16B chunks over 256 threads = 8 each
    auto load_stage = [&](int ks, int buf) {
        const uint32_t sbase = sb + buf * GSTAGE_B;
        const int ch  = tid & 3;
        const int rlo = tid >> 2;                 // 0..63
#pragma unroll
        for (int t = 0; t < 8; t++) {
            const int which = t >> 1;             // 0:Ahi 1:Alo 2:Bhi 3:Blo
            const int r     = (t & 1) * 64 + rlo; // 0..127
            const int chs   = ch ^ ((r ^ (r >> 2)) & 3);
            const __nv_bfloat16* src;
            if (which == 0)      src = Ahi + (size_t)(bm + r) * K;
            else if (which == 1) src = Alo + (size_t)(bm + r) * K;
            else if (which == 2) src = Bhi + (size_t)(bn + r) * K;
            else                 src = Blo + (size_t)(bn + r) * K;
            src += ks * 32 + ch * 8;
            uint32_t dst = sbase + which * 8192 + r * 64 + chs * 16;
            CP_ASYNC16(dst, src);
        }
    };

    auto compute = [&](int buf) {
        const uint32_t Ab  = sb + buf * GSTAGE_B;
        const uint32_t Alb = Ab + 8192;
        const uint32_t Bb  = Ab + 16384;
        const uint32_t Blb = Ab + 24576;
#pragma unroll
        for (int ks = 0; ks < 2; ks++) {
            uint32_t ah[4][4], al[4][4], bh[2][4], bl[2][4];
#pragma unroll
            for (int i = 0; i < 4; i++) {
                LDSM4(ah[i], Ab  + offA[i][ks]);
                LDSM4(al[i], Alb + offA[i][ks]);
            }
#pragma unroll
            for (int p = 0; p < 2; p++) {
                LDSM4(bh[p], Bb  + offB[p][ks]);
                LDSM4(bl[p], Blb + offB[p][ks]);
            }
#pragma unroll
            for (int i = 0; i < 4; i++)
#pragma unroll
                for (int j = 0; j < 4; j++) {
                    const int p = j >> 1, o = j & 1;
                    MMA16816(acc[i][j], ah[i], bh[p][o], bh[p][o + 2]);
                    MMA16816(acc[i][j], ah[i], bl[p][o], bl[p][o + 2]);
                    MMA16816(acc[i][j], al[i], bh[p][o], bh[p][o + 2]);
                }
        }
    };

    const int nst = K >> 5;   // K/32 stages
#pragma unroll
    for (int p = 0; p < 3; p++) {
        if (p < nst) load_stage(p, p);
        CP_COMMIT();
    }
    for (int s = 0; s < nst; s++) {
        CP_WAIT2();
        __syncthreads();
        const int np = s + 3;
        if (np < nst) load_stage(np, np & 3);
        CP_COMMIT();
        compute(s & 3);
    }

    // epilogue: direct STG float2 per fragment row (+bias)
#pragma unroll
    for (int i = 0; i < 4; i++) {
        const int row = bm + m0 + i * 16 + (lane >> 2);
#pragma unroll
        for (int j = 0; j < 4; j++) {
            const int col = bn + n0 + j * 8 + (lane & 3) * 2;
            float b0 = 0.f, b1 = 0.f;
            if (HAS_BIAS) { b0 = bias[col]; b1 = bias[col + 1]; }
            float2 v;
            v.x = acc[i][j][0] + b0; v.y = acc[i][j][1] + b1;
            *(float2*)(C + (size_t)row * N + col) = v;
            v.x = acc[i][j][2] + b0; v.y = acc[i][j][3] + b1;
            *(float2*)(C + (size_t)(row + 8) * N + col) = v;
        }
    }
}

// ---------------- RoPE (neox) + kv_fused scatter ----------------
__global__ void rope_scatter(const int* __restrict__ positions,
                             float* __restrict__ kv_out)
{
    int idx = blockIdx.x * blockDim.x + threadIdx.x;
    const int total = TOK * 36 * 64;
    if (idx >= total) return;
    int d = idx & 63;
    int h = (idx >> 6) % 36;
    int t = idx / (36 * 64);

    if (h >= 32) {
        int vh = h - 32;
        const float* src = g_vraw + (size_t)t * NKVD + vh * HDIM;
        float* dst = kv_out + ((size_t)t * 8 + 4 + vh) * HDIM;
        dst[d]      = src[d];
        dst[d + 64] = src[d + 64];
        return;
    }

    int pos = positions[t];
    float inv = exp2f((float)d * -0.31143075693324f);  // theta^(-d/64)
    float ang = (float)pos * inv;
    float sv, cv;
    sincosf(ang, &sv, &cv);

    if (h < 28) {
        float* base = g_qraw + (size_t)t * NQK + h * HDIM;
        float x1 = base[d], x2 = base[d + 64];
        base[d]      = (x1 * cv - x2 * sv) * QSCALE;
        base[d + 64] = (x2 * cv + x1 * sv) * QSCALE;
    } else {
        int kh = h - 28;
        const float* src = g_kraw + (size_t)t * NKVD + kh * HDIM;
        float x1 = src[d], x2 = src[d + 64];
        float* dst = kv_out + ((size_t)t * 8 + kh) * HDIM;
        dst[d]      = x1 * cv - x2 * sv;
        dst[d + 64] = x2 * cv + x1 * sv;
    }
}

// ---------------- causal GQA flash attention (fp32) ----------------
#define ATTN_SMEM_FLOATS (2 * 64 * 132 + 64 * 128 + 64 * 65)
#define ATTN_SMEM_BYTES  (ATTN_SMEM_FLOATS * 4)

__global__ __launch_bounds__(256) void attn_kernel(const float* __restrict__ kv)
{
    extern __shared__ float sm[];
    float (*Qs)[132] = (float (*)[132])(sm);
    float (*Ks)[132] = (float (*)[132])(sm + 64 * 132);
    float (*Vs)[128] = (float (*)[128])(sm + 2 * 64 * 132);
    float (*Ps)[65]  = (float (*)[65]) (sm + 2 * 64 * 132 + 64 * 128);

    const int qt  = blockIdx.x;
    const int qh  = blockIdx.y;
    const int b   = blockIdx.z;
    const int kvh = qh / GQA;
    const int tid = threadIdx.x;
    const int tx  = tid & 15;
    const int ty  = tid >> 4;
    const int t0  = b * SEQL + qt * 64;

    for (int s = tid; s < 64 * 32; s += 256) {
        int r = s >> 5, c = (s & 31) * 4;
        float4 v = *(const float4*)(g_qraw + ((size_t)(t0 + r) * NQH + qh) * HDIM + c);
        *(float4*)&Qs[r][c] = v;
    }

    float m_run[4], l_run[4], acc[4][8];
#pragma unroll
    for (int i = 0; i < 4; i++) {
        m_run[i] = -1e30f; l_run[i] = 0.f;
#pragma unroll
        for (int j = 0; j < 8; j++) acc[i][j] = 0.f;
    }

    for (int kt = 0; kt <= qt; kt++) {
        __syncthreads();
        for (int s = tid; s < 64 * 32; s += 256) {
            int r = s >> 5, c = (s & 31) * 4;
            int t = b * SEQL + kt * 64 + r;
            *(float4*)&Ks[r][c] = *(const float4*)(kv + ((size_t)t * 8 + kvh) * HDIM + c);
            *(float4*)&Vs[r][c] = *(const float4*)(kv + ((size_t)t * 8 + 4 + kvh) * HDIM + c);
        }
        __syncthreads();

        float sc[4][4];
#pragma unroll
        for (int i = 0; i < 4; i++)
#pragma unroll
            for (int j = 0; j < 4; j++) sc[i][j] = 0.f;

        for (int c = 0; c < HDIM; c += 4) {
            float4 qv[4], kk[4];
#pragma unroll
            for (int i = 0; i < 4; i++) qv[i] = *(const float4*)&Qs[ty + 16 * i][c];
#pragma unroll
            for (int j = 0; j < 4; j++) kk[j] = *(const float4*)&Ks[tx + 16 * j][c];
#pragma unroll
            for (int i = 0; i < 4; i++)
#pragma unroll
                for (int j = 0; j < 4; j++)
                    sc[i][j] += qv[i].x * kk[j].x + qv[i].y * kk[j].y +
                                qv[i].z * kk[j].z + qv[i].w * kk[j].w;
        }

        if (kt == qt) {
#pragma unroll
            for (int i = 0; i < 4; i++)
#pragma unroll
                for (int j = 0; j < 4; j++)
                    if (tx + 16 * j > ty + 16 * i) sc[i][j] = -1e30f;
        }

#pragma unroll
        for (int i = 0; i < 4; i++) {
            float mloc = fmaxf(fmaxf(sc[i][0], sc[i][1]), fmaxf(sc[i][2], sc[i][3]));
#pragma unroll
            for (int off = 8; off >= 1; off >>= 1)
                mloc = fmaxf(mloc, __shfl_xor_sync(0xffffffffu, mloc, off));
            float m_new = fmaxf(m_run[i], mloc);
            float alpha = __expf(m_run[i] - m_new);
            m_run[i] = m_new;
            float psum = 0.f;
#pragma unroll
            for (int j = 0; j < 4; j++) {
                float p = __expf(sc[i][j] - m_new);
                Ps[ty + 16 * i][tx + 16 * j] = p;
                psum += p;
            }
#pragma unroll
            for (int off = 8; off >= 1; off >>= 1)
                psum += __shfl_xor_sync(0xffffffffu, psum, off);
            l_run[i] = l_run[i] * alpha + psum;
#pragma unroll
            for (int j = 0; j < 8; j++) acc[i][j] *= alpha;
        }
        __syncthreads();

        for (int k = 0; k < 64; k++) {
            float4 v0 = *(const float4*)&Vs[k][tx * 8];
            float4 v1 = *(const float4*)&Vs[k][tx * 8 + 4];
#pragma unroll
            for (int i = 0; i < 4; i++) {
                float p = Ps[ty + 16 * i][k];
                acc[i][0] += p * v0.x; acc[i][1] += p * v0.y;
                acc[i][2] += p * v0.z; acc[i][3] += p * v0.w;
                acc[i][4] += p * v1.x; acc[i][5] += p * v1.y;
                acc[i][6] += p * v1.z; acc[i][7] += p * v1.w;
            }
        }
    }

#pragma unroll
    for (int i = 0; i < 4; i++) {
        float inv_l = 1.f / l_run[i];
        int row = t0 + ty + 16 * i;
        float* dst = g_attn + (size_t)row * HID + qh * HDIM + tx * 8;
        float4 o0, o1;
        o0.x = acc[i][0] * inv_l; o0.y = acc[i][1] * inv_l;
        o0.z = acc[i][2] * inv_l; o0.w = acc[i][3] * inv_l;
        o1.x = acc[i][4] * inv_l; o1.y = acc[i][5] * inv_l;
        o1.z = acc[i][6] * inv_l; o1.w = acc[i][7] * inv_l;
        *(float4*)(dst)     = o0;
        *(float4*)(dst + 4) = o1;
    }
}

// ---------------- launch ----------------
extern "C" void kernel_launch(void* const* d_in, const int* in_sizes, int n_in,
                              void* d_out, int out_size)
{
    const float* hidden    = (const float*)d_in[0];
    const int*   positions = (const int*)  d_in[1];
    const float* wq        = (const float*)d_in[2];
    const float* bq        = (const float*)d_in[3];
    const float* wk        = (const float*)d_in[4];
    const float* bk        = (const float*)d_in[5];
    const float* wv        = (const float*)d_in[6];
    const float* bv        = (const float*)d_in[7];
    const float* wo        = (const float*)d_in[8];
    (void)in_sizes; (void)n_in; (void)out_size;

    float* out    = (float*)d_out;                 // [T, HID]
    float* out_kv = out + (size_t)TOK * HID;       // [T, 8, 128] kv_fused

    float *qraw, *kraw, *vraw, *attnb;
    cudaGetSymbolAddress((void**)&qraw,  g_qraw);
    cudaGetSymbolAddress((void**)&kraw,  g_kraw);
    cudaGetSymbolAddress((void**)&vraw,  g_vraw);
    cudaGetSymbolAddress((void**)&attnb, g_attn);

    __nv_bfloat16 *hid_hi, *hid_lo, *wqt_hi, *wqt_lo, *wkt_hi, *wkt_lo;
    __nv_bfloat16 *wvt_hi, *wvt_lo, *wot_hi, *wot_lo, *att_hi, *att_lo;
    cudaGetSymbolAddress((void**)&hid_hi, g_hid_hi);
    cudaGetSymbolAddress((void**)&hid_lo, g_hid_lo);
    cudaGetSymbolAddress((void**)&wqt_hi, g_wqt_hi);
    cudaGetSymbolAddress((void**)&wqt_lo, g_wqt_lo);
    cudaGetSymbolAddress((void**)&wkt_hi, g_wkt_hi);
    cudaGetSymbolAddress((void**)&wkt_lo, g_wkt_lo);
    cudaGetSymbolAddress((void**)&wvt_hi, g_wvt_hi);
    cudaGetSymbolAddress((void**)&wvt_lo, g_wvt_lo);
    cudaGetSymbolAddress((void**)&wot_hi, g_wot_hi);
    cudaGetSymbolAddress((void**)&wot_lo, g_wot_lo);
    cudaGetSymbolAddress((void**)&att_hi, g_att_hi);
    cudaGetSymbolAddress((void**)&att_lo, g_att_lo);

    cudaFuncSetAttribute(attn_kernel, cudaFuncAttributeMaxDynamicSharedMemorySize, ATTN_SMEM_BYTES);
    cudaFuncSetAttribute(gemm_hmma<true>,  cudaFuncAttributeMaxDynamicSharedMemorySize, GSMEM_B);
    cudaFuncSetAttribute(gemm_hmma<false>, cudaFuncAttributeMaxDynamicSharedMemorySize, GSMEM_B);

    // split conversions
    split_convert<<<(TOK * HID / 4 + 255) / 256, 256>>>(hidden, hid_hi, hid_lo, TOK * HID);
    // B[n][k] = W[k][n]: dst [C,R] with src [R,C] -> (src, R=rows(src), C=cols(src))
    split_transpose<<<dim3(NQK / 32,  HID / 32), 256>>>(wq, wqt_hi, wqt_lo, HID, NQK);
    split_transpose<<<dim3(NKVD / 32, HID / 32), 256>>>(wk, wkt_hi, wkt_lo, HID, NKVD);
    split_transpose<<<dim3(NKVD / 32, HID / 32), 256>>>(wv, wvt_hi, wvt_lo, HID, NKVD);
    // wo is [NQK, HID]; need B[n=HID][k=NQK] = wo[k][n] -> src R=NQK, C=HID
    split_transpose<<<dim3(HID / 32,  NQK / 32), 256>>>(wo, wot_hi, wot_lo, NQK, HID);

    // QKV projections (+bias) on tensor cores (HMMA bf16x3)
    gemm_hmma<true><<<dim3(NQK / 128, TOK / 128), 256, GSMEM_B>>>(
        hid_hi, hid_lo, wqt_hi, wqt_lo, bq, qraw, NQK, HID);
    gemm_hmma<true><<<dim3(NKVD / 128, TOK / 128), 256, GSMEM_B>>>(
        hid_hi, hid_lo, wkt_hi, wkt_lo, bk, kraw, NKVD, HID);
    gemm_hmma<true><<<dim3(NKVD / 128, TOK / 128), 256, GSMEM_B>>>(
        hid_hi, hid_lo, wvt_hi, wvt_lo, bv, vraw, NKVD, HID);

    // RoPE + kv_fused output
    rope_scatter<<<(TOK * 36 * 64 + 255) / 256, 256>>>(positions, out_kv);

    // causal GQA flash attention (fp32)
    attn_kernel<<<dim3(SEQL / 64, NQH, 4), 256, ATTN_SMEM_BYTES>>>(out_kv);

    // o_proj on tensor cores
    split_convert<<<(TOK * HID / 4 + 255) / 256, 256>>>(attnb, att_hi, att_lo, TOK * HID);
    gemm_hmma<false><<<dim3(HID / 128, TOK / 128), 256, GSMEM_B>>>(
        att_hi, att_lo, wot_hi, wot_lo, nullptr, out, HID, HID);
}

// round 4
// speedup vs baseline: 2.8734x; 1.5991x over previous
#include <cuda_runtime.h>
#include <cuda_bf16.h>
#include <math.h>
#include <stdint.h>

#define TOK    4096
#define HID    3584
#define NQH    28
#define NKVH   4
#define HDIM   128
#define SEQL   1024
#define GQA    7
#define QSCALE 0.08838834764831845f   // 1/sqrt(128)
#define NQK    (NQH * HDIM)           // 3584
#define NKVD   (NKVH * HDIM)          // 512
#define NQKV   (NQK + 2 * NKVD)       // 4608

// ---------------- scratch (device globals) ----------------
__device__ float g_qkv[(size_t)TOK * NQKV];     // fused QKV projection output (fp32)
__device__ float g_bqkv[NQKV];                  // concat bias

__device__ __nv_bfloat16 g_hid_hi[(size_t)TOK * HID];
__device__ __nv_bfloat16 g_hid_lo[(size_t)TOK * HID];
__device__ __nv_bfloat16 g_wqkvt_hi[(size_t)NQKV * HID];
__device__ __nv_bfloat16 g_wqkvt_lo[(size_t)NQKV * HID];
__device__ __nv_bfloat16 g_wot_hi[(size_t)HID * NQK];
__device__ __nv_bfloat16 g_wot_lo[(size_t)HID * NQK];

__device__ __nv_bfloat16 g_q_hi[(size_t)TOK * NQK];   // roped+scaled Q
__device__ __nv_bfloat16 g_q_lo[(size_t)TOK * NQK];
__device__ __nv_bfloat16 g_k_hi[(size_t)TOK * NKVD];  // roped K
__device__ __nv_bfloat16 g_k_lo[(size_t)TOK * NKVD];
__device__ __nv_bfloat16 g_v_hi[(size_t)TOK * NKVD];
__device__ __nv_bfloat16 g_v_lo[(size_t)TOK * NKVD];
__device__ __nv_bfloat16 g_att_hi[(size_t)TOK * NQK]; // attention out
__device__ __nv_bfloat16 g_att_lo[(size_t)TOK * NQK];

// ==================== PTX helpers ====================
__device__ __forceinline__ uint32_t smem_to_u32(const void* p) {
    uint32_t a;
    asm("{ .reg .u64 t; cvta.to.shared.u64 t, %1; cvt.u32.u64 %0, t; }" : "=r"(a) : "l"(p));
    return a;
}
#define CP_ASYNC16(dst, src) \
    asm volatile("cp.async.cg.shared.global [%0], [%1], 16;" :: "r"(dst), "l"(src))
#define CP_COMMIT() asm volatile("cp.async.commit_group;" ::: "memory")
#define CP_WAIT0()  asm volatile("cp.async.wait_group 0;" ::: "memory")
#define CP_WAIT1()  asm volatile("cp.async.wait_group 1;" ::: "memory")

#define LDSM4(r, addr) \
    asm volatile("ldmatrix.sync.aligned.m8n8.x4.shared.b16 {%0,%1,%2,%3}, [%4];" \
        : "=r"((r)[0]), "=r"((r)[1]), "=r"((r)[2]), "=r"((r)[3]) : "r"(addr))
#define LDSM4T(r, addr) \
    asm volatile("ldmatrix.sync.aligned.m8n8.x4.trans.shared.b16 {%0,%1,%2,%3}, [%4];" \
        : "=r"((r)[0]), "=r"((r)[1]), "=r"((r)[2]), "=r"((r)[3]) : "r"(addr))

#define MMA16816(d, a, b0, b1) \
    asm volatile("mma.sync.aligned.m16n8k16.row.col.f32.bf16.bf16.f32 " \
        "{%0,%1,%2,%3}, {%4,%5,%6,%7}, {%8,%9}, {%0,%1,%2,%3};" \
        : "+f"((d)[0]), "+f"((d)[1]), "+f"((d)[2]), "+f"((d)[3]) \
        : "r"((a)[0]), "r"((a)[1]), "r"((a)[2]), "r"((a)[3]), "r"(b0), "r"(b1))

__device__ __forceinline__ uint32_t pack_bf16x2(float a, float b) {
    __nv_bfloat162 h = __floats2bfloat162_rn(a, b);
    return *(uint32_t*)&h;
}

// ==================== split/convert kernels ====================
__global__ void split_convert(const float* __restrict__ src,
                              __nv_bfloat16* __restrict__ hi,
                              __nv_bfloat16* __restrict__ lo, int n)
{
    int i = (blockIdx.x * blockDim.x + threadIdx.x) * 4;
    if (i >= n) return;
    float4 v = *(const float4*)(src + i);
    __nv_bfloat16 h0 = __float2bfloat16(v.x), h1 = __float2bfloat16(v.y);
    __nv_bfloat16 h2 = __float2bfloat16(v.z), h3 = __float2bfloat16(v.w);
    __nv_bfloat16 l0 = __float2bfloat16(v.x - __bfloat162float(h0));
    __nv_bfloat16 l1 = __float2bfloat16(v.y - __bfloat162float(h1));
    __nv_bfloat16 l2 = __float2bfloat16(v.z - __bfloat162float(h2));
    __nv_bfloat16 l3 = __float2bfloat16(v.w - __bfloat162float(h3));
    *(__nv_bfloat162*)(hi + i)     = __nv_bfloat162(h0, h1);
    *(__nv_bfloat162*)(hi + i + 2) = __nv_bfloat162(h2, h3);
    *(__nv_bfloat162*)(lo + i)     = __nv_bfloat162(l0, l1);
    *(__nv_bfloat162*)(lo + i + 2) = __nv_bfloat162(l2, l3);
}

// src [R, C] fp32 -> dst [C, R] bf16 hi/lo
__global__ void split_transpose(const float* __restrict__ src,
                                __nv_bfloat16* __restrict__ hi,
                                __nv_bfloat16* __restrict__ lo, int R, int C)
{
    __shared__ float t[32][33];
    const int tx = threadIdx.x & 31;
    const int ty = threadIdx.x >> 5;
    const int r0 = blockIdx.y * 32;
    const int c0 = blockIdx.x * 32;
#pragma unroll
    for (int i = 0; i < 4; i++) {
        int r = ty + 8 * i;
        t[r][tx] = src[(size_t)(r0 + r) * C + c0 + tx];
    }
    __syncthreads();
#pragma unroll
    for (int i = 0; i < 4; i++) {
        int r = ty + 8 * i;
        float x = t[tx][r];
        __nv_bfloat16 h = __float2bfloat16(x);
        __nv_bfloat16 l = __float2bfloat16(x - __bfloat162float(h));
        size_t o = (size_t)(c0 + r) * R + r0 + tx;
        hi[o] = h;
        lo[o] = l;
    }
}

__global__ void concat_bias(const float* __restrict__ bq, const float* __restrict__ bk,
                            const float* __restrict__ bv, float* __restrict__ dst)
{
    int i = blockIdx.x * blockDim.x + threadIdx.x;
    if (i >= NQKV) return;
    if (i < NQK)            dst[i] = bq[i];
    else if (i < NQK + NKVD) dst[i] = bk[i - NQK];
    else                     dst[i] = bv[i - NQK - NKVD];
}

// ==================== HMMA bf16x3 GEMM, 128x256 tile, 3-stage ====================
// C[M,N] = A[M,K]*B[N,K]^T (+bias). 8 warps (2M x 4N), warp tile 64x64.
// stage: Ahi/Alo 128x32 (8KB each) + Bhi/Blo 256x32 (16KB each) = 48KB; x3 = 144KB.
#define G2_AHI 0
#define G2_ALO 8192
#define G2_BHI 16384
#define G2_BLO 32768
#define G2_STAGE 49152
#define G2_SMEM (3 * G2_STAGE)

template <bool HAS_BIAS>
__global__ __launch_bounds__(256, 1) void gemm_hmma256(
    const __nv_bfloat16* __restrict__ Ahi, const __nv_bfloat16* __restrict__ Alo,
    const __nv_bfloat16* __restrict__ Bhi, const __nv_bfloat16* __restrict__ Blo,
    const float* __restrict__ bias, float* __restrict__ C, int N, int K)
{
    extern __shared__ char smem[];
    const uint32_t sb = smem_to_u32(smem);
    const int tid  = threadIdx.x;
    const int wid  = tid >> 5;
    const int lane = tid & 31;
    const int bn   = blockIdx.x * 256;
    const int bm   = blockIdx.y * 128;
    const int m0   = (wid >> 2) * 64;
    const int n0   = (wid & 3) * 64;

    float acc[4][8][4];
#pragma unroll
    for (int i = 0; i < 4; i++)
#pragma unroll
        for (int j = 0; j < 8; j++)
#pragma unroll
            for (int r = 0; r < 4; r++) acc[i][j][r] = 0.f;

    // loader: 3072 16B-chunks per stage / 256 threads = 12 each
    auto load_stage = [&](int ks, int buf) {
        const uint32_t sbase = sb + buf * G2_STAGE;
#pragma unroll
        for (int u = 0; u < 12; u++) {
            const int s = u * 256 + tid;
            const __nv_bfloat16* src;
            uint32_t dbase;
            int r, ch;
            if (s < 1024) {            // A: 2 bufs x 512 chunks
                const int bsel = s >> 9, idx = s & 511;
                r = idx >> 2; ch = idx & 3;
                src = (bsel ? Alo : Ahi) + (size_t)(bm + r) * K;
                dbase = bsel ? G2_ALO : G2_AHI;
            } else {                   // B: 2 bufs x 1024 chunks
                const int t2 = s - 1024;
                const int bsel = t2 >> 10, idx = t2 & 1023;
                r = idx >> 2; ch = idx & 3;
                src = (bsel ? Blo : Bhi) + (size_t)(bn + r) * K;
                dbase = bsel ? G2_BLO : G2_BHI;
            }
            const int chs = ch ^ ((r ^ (r >> 2)) & 3);
            CP_ASYNC16(sbase + dbase + r * 64 + chs * 16, src + ks * 32 + ch * 8);
        }
    };

    auto compute = [&](int buf) {
        const uint32_t st = sb + buf * G2_STAGE;
#pragma unroll
        for (int ks = 0; ks < 2; ks++) {
            uint32_t ah[4][4], al[4][4];
#pragma unroll
            for (int i = 0; i < 4; i++) {
                const int row = m0 + i * 16 + (lane & 15);
                const int ch  = (ks * 2 + (lane >> 4)) ^ ((row ^ (row >> 2)) & 3);
                LDSM4(ah[i], st + G2_AHI + row * 64 + ch * 16);
                LDSM4(al[i], st + G2_ALO + row * 64 + ch * 16);
            }
#pragma unroll
            for (int nb = 0; nb < 4; nb++) {
                const int row = n0 + nb * 16 + ((lane >> 3) & 1) * 8 + (lane & 7);
                const int ch  = (ks * 2 + (lane >> 4)) ^ ((row ^ (row >> 2)) & 3);
                uint32_t bh[4], bl[4];
                LDSM4(bh, st + G2_BHI + row * 64 + ch * 16);
                LDSM4(bl, st + G2_BLO + row * 64 + ch * 16);
#pragma unroll
                for (int i = 0; i < 4; i++) {
                    MMA16816(acc[i][nb * 2],     ah[i], bh[0], bh[2]);
                    MMA16816(acc[i][nb * 2],     ah[i], bl[0], bl[2]);
                    MMA16816(acc[i][nb * 2],     al[i], bh[0], bh[2]);
                    MMA16816(acc[i][nb * 2 + 1], ah[i], bh[1], bh[3]);
                    MMA16816(acc[i][nb * 2 + 1], ah[i], bl[1], bl[3]);
                    MMA16816(acc[i][nb * 2 + 1], al[i], bh[1], bh[3]);
                }
            }
        }
    };

    const int nst = K >> 5;
    load_stage(0, 0); CP_COMMIT();
    load_stage(1, 1); CP_COMMIT();
    int buf = 0;
    for (int s = 0; s < nst; s++) {
        CP_WAIT1();
        __syncthreads();
        const int np = s + 2;
        if (np < nst) { load_stage(np, (buf + 2) % 3); }
        CP_COMMIT();
        compute(buf);
        buf = (buf + 1) % 3;
    }

    // epilogue
#pragma unroll
    for (int i = 0; i < 4; i++) {
        const int row = bm + m0 + i * 16 + (lane >> 2);
#pragma unroll
        for (int j = 0; j < 8; j++) {
            const int col = bn + n0 + j * 8 + (lane & 3) * 2;
            float b0 = 0.f, b1 = 0.f;
            if (HAS_BIAS) { b0 = bias[col]; b1 = bias[col + 1]; }
            float2 v;
            v.x = acc[i][j][0] + b0; v.y = acc[i][j][1] + b1;
            *(float2*)(C + (size_t)row * N + col) = v;
            v.x = acc[i][j][2] + b0; v.y = acc[i][j][3] + b1;
            *(float2*)(C + (size_t)(row + 8) * N + col) = v;
        }
    }
}

// ---------------- RoPE + kv_fused scatter + bf16 split ----------------
__global__ void rope_scatter(const int* __restrict__ positions,
                             float* __restrict__ kv_out)
{
    int idx = blockIdx.x * blockDim.x + threadIdx.x;
    const int total = TOK * 36 * 64;
    if (idx >= total) return;
    int d = idx & 63;
    int h = (idx >> 6) % 36;
    int t = idx / (36 * 64);

    if (h >= 32) {   // V: copy + split
        int vh = h - 32;
        const float* src = g_qkv + (size_t)t * NQKV + NQK + NKVD + vh * HDIM;
        float* dst = kv_out + ((size_t)t * 8 + 4 + vh) * HDIM;
        size_t bo = (size_t)t * NKVD + vh * HDIM;
        float x1 = src[d], x2 = src[d + 64];
        dst[d] = x1; dst[d + 64] = x2;
        __nv_bfloat16 h1 = __float2bfloat16(x1), h2 = __float2bfloat16(x2);
        g_v_hi[bo + d]      = h1;
        g_v_lo[bo + d]      = __float2bfloat16(x1 - __bfloat162float(h1));
        g_v_hi[bo + d + 64] = h2;
        g_v_lo[bo + d + 64] = __float2bfloat16(x2 - __bfloat162float(h2));
        return;
    }

    int pos = positions[t];
    float inv = exp2f((float)d * -0.31143075693324f);  // theta^(-d/64)
    float ang = (float)pos * inv;
    float sv, cv;
    sincosf(ang, &sv, &cv);

    if (h < 28) {    // Q: rope + scale + split
        const float* src = g_qkv + (size_t)t * NQKV + h * HDIM;
        float x1 = src[d], x2 = src[d + 64];
        float y1 = (x1 * cv - x2 * sv) * QSCALE;
        float y2 = (x2 * cv + x1 * sv) * QSCALE;
        size_t bo = (size_t)t * NQK + h * HDIM;
        __nv_bfloat16 h1 = __float2bfloat16(y1), h2 = __float2bfloat16(y2);
        g_q_hi[bo + d]      = h1;
        g_q_lo[bo + d]      = __float2bfloat16(y1 - __bfloat162float(h1));
        g_q_hi[bo + d + 64] = h2;
        g_q_lo[bo + d + 64] = __float2bfloat16(y2 - __bfloat162float(h2));
    } else {         // K: rope + output + split
        int kh = h - 28;
        const float* src = g_qkv + (size_t)t * NQKV + NQK + kh * HDIM;
        float x1 = src[d], x2 = src[d + 64];
        float y1 = x1 * cv - x2 * sv;
        float y2 = x2 * cv + x1 * sv;
        float* dst = kv_out + ((size_t)t * 8 + kh) * HDIM;
        dst[d] = y1; dst[d + 64] = y2;
        size_t bo = (size_t)t * NKVD + kh * HDIM;
        __nv_bfloat16 h1 = __float2bfloat16(y1), h2 = __float2bfloat16(y2);
        g_k_hi[bo + d]      = h1;
        g_k_lo[bo + d]      = __float2bfloat16(y1 - __bfloat162float(h1));
        g_k_hi[bo + d + 64] = h2;
        g_k_lo[bo + d + 64] = __float2bfloat16(y2 - __bfloat162float(h2));
    }
}

// ==================== HMMA flash attention ====================
// block: 128 q rows x 64 k per iter; 8 warps, each a 16-row stripe.
// smem (swizzled 256B rows, chunk ^= row&7):
//   Qhi 0, Qlo 32768, Khi 65536, Klo 81920, Vhi 98304, Vlo 114688  -> 128KB
#define A_QHI 0
#define A_QLO 32768
#define A_KHI 65536
#define A_KLO 81920
#define A_VHI 98304
#define A_VLO 114688
#define A_SMEM 131072

__global__ __launch_bounds__(256, 1) void attn_hmma()
{
    extern __shared__ char smem[];
    const uint32_t sb = smem_to_u32(smem);
    const int tid  = threadIdx.x;
    const int wid  = tid >> 5;
    const int lane = tid & 31;
    const int qh   = blockIdx.x;
    const int qt   = (gridDim.y - 1) - blockIdx.y;  // heavy tiles first
    const int b    = blockIdx.z;
    const int kvh  = qh / GQA;
    const int t0   = b * SEQL + qt * 128;

    // load Q tile (128 x 256B, hi+lo)
#pragma unroll
    for (int u = 0; u < 16; u++) {
        const int s   = u * 256 + tid;
        const int bsel = s >> 11;
        const int r   = (s >> 4) & 127;
        const int ch  = s & 15;
        const __nv_bfloat16* src =
            (bsel ? g_q_lo : g_q_hi) + (size_t)(t0 + r) * NQK + qh * HDIM + ch * 8;
        CP_ASYNC16(sb + (bsel ? A_QLO : A_QHI) + r * 256 + ((ch ^ (r & 7)) * 16), src);
    }
    CP_COMMIT();

    float m_run[2] = {-1e30f, -1e30f};
    float l_run[2] = {0.f, 0.f};
    float acc[16][4];
#pragma unroll
    for (int nt = 0; nt < 16; nt++)
#pragma unroll
        for (int r = 0; r < 4; r++) acc[nt][r] = 0.f;

    const int arow   = wid * 16 + (lane & 15);
    const int brow_b = ((lane >> 3) & 1) * 8 + (lane & 7);
    const int ktmax  = 2 * qt + 2;

    for (int kt = 0; kt < ktmax; kt++) {
        __syncthreads();
        // load K/V tiles (4 bufs x 64 rows x 16 chunks)
        const int tk = b * SEQL + kt * 64;
#pragma unroll
        for (int u = 0; u < 16; u++) {
            const int s    = u * 256 + tid;
            const int bsel = s >> 10;           // 0:Khi 1:Klo 2:Vhi 3:Vlo
            const int r    = (s >> 4) & 63;
            const int ch   = s & 15;
            const __nv_bfloat16* base =
                (bsel == 0) ? g_k_hi : (bsel == 1) ? g_k_lo : (bsel == 2) ? g_v_hi : g_v_lo;
            const __nv_bfloat16* src = base + (size_t)(tk + r) * NKVD + kvh * HDIM + ch * 8;
            CP_ASYNC16(sb + A_KHI + bsel * 16384 + r * 256 + ((ch ^ (r & 7)) * 16), src);
        }
        CP_COMMIT();
        CP_WAIT0();
        __syncthreads();

        // S = Q K^T (bf16x3)
        float s_acc[8][4];
#pragma unroll
        for (int nt = 0; nt < 8; nt++)
#pragma unroll
            for (int r = 0; r < 4; r++) s_acc[nt][r] = 0.f;

#pragma unroll
        for (int ks = 0; ks < 8; ks++) {
            uint32_t ah[4], al[4];
            const uint32_t aoff = arow * 256 + (((ks * 2 + (lane >> 4)) ^ (arow & 7)) * 16);
            LDSM4(ah, sb + A_QHI + aoff);
            LDSM4(al, sb + A_QLO + aoff);
#pragma unroll
            for (int nb = 0; nb < 4; nb++) {
                const int brow = nb * 16 + brow_b;
                const uint32_t boff = brow * 256 + (((ks * 2 + (lane >> 4)) ^ (brow & 7)) * 16);
                uint32_t bh[4], bl[4];
                LDSM4(bh, sb + A_KHI + boff);
                LDSM4(bl, sb + A_KLO + boff);
                MMA16816(s_acc[nb * 2],     ah, bh[0], bh[2]);
                MMA16816(s_acc[nb * 2],     ah, bl[0], bl[2]);
                MMA16816(s_acc[nb * 2],     al, bh[0], bh[2]);
                MMA16816(s_acc[nb * 2 + 1], ah, bh[1], bh[3]);
                MMA16816(s_acc[nb * 2 + 1], ah, bl[1], bl[3]);
                MMA16816(s_acc[nb * 2 + 1], al, bh[1], bh[3]);
            }
        }

        // causal mask (only diagonal-crossing tiles)
        if (kt >= 2 * qt) {
            const int row0 = qt * 128 + wid * 16 + (lane >> 2);
            const int colb = kt * 64 + (lane & 3) * 2;
#pragma unroll
            for (int nt = 0; nt < 8; nt++) {
                const int c0 = colb + nt * 8;
                if (c0     > row0)     s_acc[nt][0] = -1e30f;
                if (c0 + 1 > row0)     s_acc[nt][1] = -1e30f;
                if (c0     > row0 + 8) s_acc[nt][2] = -1e30f;
                if (c0 + 1 > row0 + 8) s_acc[nt][3] = -1e30f;
            }
        }

        // online softmax (2 rows per thread)
        float ml0 = -1e30f, ml1 = -1e30f;
#pragma unroll
        for (int nt = 0; nt < 8; nt++) {
            ml0 = fmaxf(ml0, fmaxf(s_acc[nt][0], s_acc[nt][1]));
            ml1 = fmaxf(ml1, fmaxf(s_acc[nt][2], s_acc[nt][3]));
        }
        ml0 = fmaxf(ml0, __shfl_xor_sync(0xffffffffu, ml0, 1));
        ml0 = fmaxf(ml0, __shfl_xor_sync(0xffffffffu, ml0, 2));
        ml1 = fmaxf(ml1, __shfl_xor_sync(0xffffffffu, ml1, 1));
        ml1 = fmaxf(ml1, __shfl_xor_sync(0xffffffffu, ml1, 2));
        const float mn0 = fmaxf(m_run[0], ml0);
        const float mn1 = fmaxf(m_run[1], ml1);
        const float al0 = __expf(m_run[0] - mn0);
        const float al1 = __expf(m_run[1] - mn1);
        m_run[0] = mn0; m_run[1] = mn1;

        float ps0 = 0.f, ps1 = 0.f;
#pragma unroll
        for (int nt = 0; nt < 8; nt++) {
            s_acc[nt][0] = __expf(s_acc[nt][0] - mn0);
            s_acc[nt][1] = __expf(s_acc[nt][1] - mn0);
            s_acc[nt][2] = __expf(s_acc[nt][2] - mn1);
            s_acc[nt][3] = __expf(s_acc[nt][3] - mn1);
            ps0 += s_acc[nt][0] + s_acc[nt][1];
            ps1 += s_acc[nt][2] + s_acc[nt][3];
        }
        ps0 += __shfl_xor_sync(0xffffffffu, ps0, 1);
        ps0 += __shfl_xor_sync(0xffffffffu, ps0, 2);
        ps1 += __shfl_xor_sync(0xffffffffu, ps1, 1);
        ps1 += __shfl_xor_sync(0xffffffffu, ps1, 2);
        l_run[0] = l_run[0] * al0 + ps0;
        l_run[1] = l_run[1] * al1 + ps1;
#pragma unroll
        for (int nt = 0; nt < 16; nt++) {
            acc[nt][0] *= al0; acc[nt][1] *= al0;
            acc[nt][2] *= al1; acc[nt][3] *= al1;
        }

        // pack P into A-fragments (hi + residual lo)
        uint32_t pa_h[4][4], pa_l[4][4];
#pragma unroll
        for (int s2 = 0; s2 < 4; s2++) {
            float* e = s_acc[2 * s2];
            float* o = s_acc[2 * s2 + 1];
            pa_h[s2][0] = pack_bf16x2(e[0], e[1]);
            pa_h[s2][1] = pack_bf16x2(e[2], e[3]);
            pa_h[s2][2] = pack_bf16x2(o[0], o[1]);
            pa_h[s2][3] = pack_bf16x2(o[2], o[3]);
#pragma unroll
            for (int q2 = 0; q2 < 4; q2++) {
                float r0 = (q2 < 2 ? e : o)[(q2 & 1) * 2]     ;
                float r1 = (q2 < 2 ? e : o)[(q2 & 1) * 2 + 1];
                __nv_bfloat162* hh = (__nv_bfloat162*)&pa_h[s2][q2];
                pa_l[s2][q2] = pack_bf16x2(r0 - __bfloat162float(hh->x),
                                           r1 - __bfloat162float(hh->y));
            }
        }

        // acc += P V  (bf16x3: Ph*Vh + Ph*Vl + Pl*Vh)
#pragma unroll
        for (int s2 = 0; s2 < 4; s2++) {
            const int vrow = s2 * 16 + brow_b;
#pragma unroll
            for (int np = 0; np < 8; np++) {
                const uint32_t voff = vrow * 256 + (((np * 2 + (lane >> 4)) ^ (vrow & 7)) * 16);
                uint32_t vh[4], vl[4];
                LDSM4T(vh, sb + A_VHI + voff);
                LDSM4T(vl, sb + A_VLO + voff);
                MMA16816(acc[np * 2],     pa_h[s2], vh[0], vh[1]);
                MMA16816(acc[np * 2],     pa_h[s2], vl[0], vl[1]);
                MMA16816(acc[np * 2],     pa_l[s2], vh[0], vh[1]);
                MMA16816(acc[np * 2 + 1], pa_h[s2], vh[2], vh[3]);
                MMA16816(acc[np * 2 + 1], pa_h[s2], vl[2], vl[3]);
                MMA16816(acc[np * 2 + 1], pa_l[s2], vh[2], vh[3]);
            }
        }
    }

    // epilogue: normalize, split to bf16 hi/lo
    const float il0 = 1.f / l_run[0];
    const float il1 = 1.f / l_run[1];
    const int row0 = t0 + wid * 16 + (lane >> 2);
#pragma unroll
    for (int nt = 0; nt < 16; nt++) {
        const int col = qh * HDIM + nt * 8 + (lane & 3) * 2;
        float o0 = acc[nt][0] * il0, o1 = acc[nt][1] * il0;
        float o2 = acc[nt][2] * il1, o3 = acc[nt][3] * il1;
        uint32_t h01 = pack_bf16x2(o0, o1);
        uint32_t h23 = pack_bf16x2(o2, o3);
        __nv_bfloat162* p01 = (__nv_bfloat162*)&h01;
        __nv_bfloat162* p23 = (__nv_bfloat162*)&h23;
        uint32_t l01 = pack_bf16x2(o0 - __bfloat162float(p01->x), o1 - __bfloat162float(p01->y));
        uint32_t l23 = pack_bf16x2(o2 - __bfloat162float(p23->x), o3 - __bfloat162float(p23->y));
        *(uint32_t*)(g_att_hi + (size_t)row0 * NQK + col)       = h01;
        *(uint32_t*)(g_att_lo + (size_t)row0 * NQK + col)       = l01;
        *(uint32_t*)(g_att_hi + (size_t)(row0 + 8) * NQK + col) = h23;
        *(uint32_t*)(g_att_lo + (size_t)(row0 + 8) * NQK + col) = l23;
    }
}

// ---------------- launch ----------------
extern "C" void kernel_launch(void* const* d_in, const int* in_sizes, int n_in,
                              void* d_out, int out_size)
{
    const float* hidden    = (const float*)d_in[0];
    const int*   positions = (const int*)  d_in[1];
    const float* wq        = (const float*)d_in[2];
    const float* bq        = (const float*)d_in[3];
    const float* wk        = (const float*)d_in[4];
    const float* bk        = (const float*)d_in[5];
    const float* wv        = (const float*)d_in[6];
    const float* bv        = (const float*)d_in[7];
    const float* wo        = (const float*)d_in[8];
    (void)in_sizes; (void)n_in; (void)out_size;

    float* out    = (float*)d_out;                 // [T, HID]
    float* out_kv = out + (size_t)TOK * HID;       // [T, 8, 128]

    float *qkv, *bqkv;
    cudaGetSymbolAddress((void**)&qkv,  g_qkv);
    cudaGetSymbolAddress((void**)&bqkv, g_bqkv);
    __nv_bfloat16 *hid_hi, *hid_lo, *wqkvt_hi, *wqkvt_lo, *wot_hi, *wot_lo, *att_hi, *att_lo;
    cudaGetSymbolAddress((void**)&hid_hi,   g_hid_hi);
    cudaGetSymbolAddress((void**)&hid_lo,   g_hid_lo);
    cudaGetSymbolAddress((void**)&wqkvt_hi, g_wqkvt_hi);
    cudaGetSymbolAddress((void**)&wqkvt_lo, g_wqkvt_lo);
    cudaGetSymbolAddress((void**)&wot_hi,   g_wot_hi);
    cudaGetSymbolAddress((void**)&wot_lo,   g_wot_lo);
    cudaGetSymbolAddress((void**)&att_hi,   g_att_hi);
    cudaGetSymbolAddress((void**)&att_lo,   g_att_lo);

    cudaFuncSetAttribute(gemm_hmma256<true>,  cudaFuncAttributeMaxDynamicSharedMemorySize, G2_SMEM);
    cudaFuncSetAttribute(gemm_hmma256<false>, cudaFuncAttributeMaxDynamicSharedMemorySize, G2_SMEM);
    cudaFuncSetAttribute(attn_hmma, cudaFuncAttributeMaxDynamicSharedMemorySize, A_SMEM);

    // conversions
    split_convert<<<(TOK * HID / 4 + 255) / 256, 256>>>(hidden, hid_hi, hid_lo, TOK * HID);
    split_transpose<<<dim3(NQK / 32,  HID / 32), 256>>>(wq, wqkvt_hi, wqkvt_lo, HID, NQK);
    split_transpose<<<dim3(NKVD / 32, HID / 32), 256>>>(
        wk, wqkvt_hi + (size_t)NQK * HID, wqkvt_lo + (size_t)NQK * HID, HID, NKVD);
    split_transpose<<<dim3(NKVD / 32, HID / 32), 256>>>(
        wv, wqkvt_hi + (size_t)(NQK + NKVD) * HID, wqkvt_lo + (size_t)(NQK + NKVD) * HID, HID, NKVD);
    split_transpose<<<dim3(HID / 32, NQK / 32), 256>>>(wo, wot_hi, wot_lo, NQK, HID);
    concat_bias<<<(NQKV + 255) / 256, 256>>>(bq, bk, bv, bqkv);

    // fused QKV projection
    gemm_hmma256<true><<<dim3(NQKV / 256, TOK / 128), 256, G2_SMEM>>>(
        hid_hi, hid_lo, wqkvt_hi, wqkvt_lo, bqkv, qkv, NQKV, HID);

    // RoPE + kv_fused output + bf16 splits
    rope_scatter<<<(TOK * 36 * 64 + 255) / 256, 256>>>(positions, out_kv);

    // HMMA flash attention
    attn_hmma<<<dim3(NQH, SEQL / 128, 4), 256, A_SMEM>>>();

    // o_proj
    gemm_hmma256<false><<<dim3(HID / 256, TOK / 128), 256, G2_SMEM>>>(
        att_hi, att_lo, wot_hi, wot_lo, nullptr, out, HID, HID);
}